// round 15
// baseline (speedup 1.0000x reference)
#include <cuda_runtime.h>
#include <cuda_bf16.h>
#include <mma.h>
#include <cstdint>
#include <math.h>

using namespace nvcuda;
typedef __nv_bfloat16 bf16;

#define BATCH 1024
#define NSUP 16
#define NLAT 6

// ---- scratch (__device__ globals; allocation forbidden) ----
__device__ __align__(256) float g_pool1[BATCH * 16 * 14 * 14];
__device__ __align__(256) float g_pool2[BATCH * 32 * 7 * 7];
__device__ __align__(256) float g_t1f [BATCH * 1024];
__device__ __align__(256) float g_inp [BATCH * 512];
__device__ __align__(256) float g_io  [BATCH * 512];   // inp + out
__device__ __align__(256) float g_li  [BATCH * 512];   // inp + lat
__device__ __align__(256) float g_outf[BATCH * 512];
// weights W^T (N x K), 3-term bf16 split
__device__ __align__(256) bf16 g_w1h[1024 * 512], g_w1m[1024 * 512], g_w1l[1024 * 512];
__device__ __align__(256) bf16 g_w2h[512 * 1024], g_w2m[512 * 1024], g_w2l[512 * 1024];
// activations, 3-term bf16 split
__device__ __align__(256) bf16 g_sah[BATCH * 512],  g_sam[BATCH * 512],  g_sal[BATCH * 512];
__device__ __align__(256) bf16 g_t1h[BATCH * 1024], g_t1m[BATCH * 1024], g_t1l[BATCH * 1024];

// 3-term split: v = h + m + l, ~24 mantissa bits total
__device__ __forceinline__ void split3(float v, bf16& h, bf16& m, bf16& l) {
    h = __float2bfloat16_rn(v);
    float r = v - __bfloat162float(h);
    m = __float2bfloat16_rn(r);
    l = __float2bfloat16_rn(r - __bfloat162float(m));
}

// ===========================================================================
// 3-term bf16-split WMMA GEMM with BIAS-FREE ACCUMULATION (frozen numerics
// from R14: rel_err 7.1e-5). Per k16: 6 MMAs (hh,hm,mh,hl,mm,lh) into a
// FRESH-ZERO temp fragment; fold into master via fp32 RN adds. This defeats
// the tensor core's truncating accumulator-add bias (measured law:
// rel_err ≈ 2.5e-4 × MMAs-per-k16 when chained over full K; temps cut 24×).
// Template BM ∈ {64, 32}: BM=64 for GEMM1 (grid 256), BM=32 for GEMM2
// (grid 256 — was 128 at BM=64, which gave zero occ-2 co-residency).
// BN=64, BK=32. 8 warps. Static smem (BM=64: 30.7KB / BM=32: 23KB), occ 2.
// ===========================================================================
template <int BM>
__global__ __launch_bounds__(256, 2) void wmma_gemm(
    const bf16* __restrict__ Ahi, const bf16* __restrict__ Ami, const bf16* __restrict__ Alo,
    const bf16* __restrict__ Bhi, const bf16* __restrict__ Bmi, const bf16* __restrict__ Blo,
    const float* __restrict__ bias,
    const float* __restrict__ add_pair, const float* __restrict__ add_aux,
    bf16* __restrict__ Chi, bf16* __restrict__ Cmi, bf16* __restrict__ Clo,
    float* __restrict__ aux_out, float* __restrict__ act_out,
    int N, int K)
{
    constexpr int RS = 40;                 // row stride in bf16 (80B rows; ldm%8==0)
    constexpr int TI = BM / 32;            // 16-row fragments per warp in M (2 or 1)
    constexpr int AT = BM * RS;            // A tile elems
    constexpr int BT = 64 * RS;            // B tile elems
    __shared__ float sbias[64];
    __shared__ __align__(32) bf16 stile[3 * AT + 3 * BT];
    bf16* sA[3] = { stile, stile + AT, stile + 2 * AT };
    bf16* sB[3] = { stile + 3 * AT, stile + 3 * AT + BT, stile + 3 * AT + 2 * BT };

    const int tid = threadIdx.x, wid = tid >> 5;
    const int bm = blockIdx.y * BM, bn = blockIdx.x * 64;
    const int warp_m = wid & 1, warp_n = wid >> 1;     // 2 x 4 warp grid
    const int m_w = warp_m * (BM / 2), n_w = warp_n * 16;
    const int KT = K >> 5;                             // BK = 32

    if (tid < 64) sbias[tid] = bias[bn + tid];

    wmma::fragment<wmma::accumulator, 16, 16, 16, float> facc[TI];
#pragma unroll
    for (int t = 0; t < TI; t++) wmma::fill_fragment(facc[t], 0.0f);

    // per-iteration register staging (BM=32: only tid<128 carry A)
    uint4 rA[3], rB[3];
    const int lrow = tid >> 2, lch = (tid & 3) * 8;    // 64 rows x 4 chunks of 8
    const bool hasA = (BM == 64) || (tid < 128);

    auto gload = [&](int kt) {
        const int kof = kt * 32;
        if (hasA) {
            size_t oa = (size_t)(bm + lrow) * K + kof + lch;
            rA[0] = *(const uint4*)(Ahi + oa);
            rA[1] = *(const uint4*)(Ami + oa);
            rA[2] = *(const uint4*)(Alo + oa);
        }
        size_t ob = (size_t)(bn + lrow) * K + kof + lch;
        rB[0] = *(const uint4*)(Bhi + ob);
        rB[1] = *(const uint4*)(Bmi + ob);
        rB[2] = *(const uint4*)(Blo + ob);
    };
    auto sstore = [&]() {
        if (hasA) {
#pragma unroll
            for (int t = 0; t < 3; t++)
                *(uint4*)(sA[t] + lrow * RS + lch) = rA[t];
        }
#pragma unroll
        for (int t = 0; t < 3; t++)
            *(uint4*)(sB[t] + lrow * RS + lch) = rB[t];
    };

    gload(0);
    sstore();
    __syncthreads();

    for (int kt = 0; kt < KT; kt++) {
        if (kt + 1 < KT) gload(kt + 1);   // prefetch next tile into registers

#pragma unroll
        for (int k16 = 0; k16 < 2; k16++) {
            const int kb = k16 * 16;
            wmma::fragment<wmma::matrix_b, 16, 16, 16, bf16, wmma::col_major> fb[3];
#pragma unroll
            for (int t = 0; t < 3; t++)
                wmma::load_matrix_sync(fb[t], sB[t] + n_w * RS + kb, RS);
#pragma unroll
            for (int ti = 0; ti < TI; ti++) {
                wmma::fragment<wmma::matrix_a, 16, 16, 16, bf16, wmma::row_major> fa[3];
#pragma unroll
                for (int t = 0; t < 3; t++)
                    wmma::load_matrix_sync(fa[t], sA[t] + (m_w + ti * 16) * RS + kb, RS);
                // fresh-zero temp: keeps |acc| small during HW chained adds
                wmma::fragment<wmma::accumulator, 16, 16, 16, float> ftmp;
                wmma::fill_fragment(ftmp, 0.0f);
                wmma::mma_sync(ftmp, fa[0], fb[0], ftmp);  // h*h
                wmma::mma_sync(ftmp, fa[0], fb[1], ftmp);  // h*m
                wmma::mma_sync(ftmp, fa[1], fb[0], ftmp);  // m*h
                wmma::mma_sync(ftmp, fa[0], fb[2], ftmp);  // h*l
                wmma::mma_sync(ftmp, fa[1], fb[1], ftmp);  // m*m
                wmma::mma_sync(ftmp, fa[2], fb[0], ftmp);  // l*h
#pragma unroll
                for (int e = 0; e < ftmp.num_elements; e++)
                    facc[ti].x[e] += ftmp.x[e];
            }
        }
        __syncthreads();
        if (kt + 1 < KT) { sstore(); __syncthreads(); }
    }

    // ---- stage C to smem (aliases tile memory; safe after the sync above) ----
    float* cs = (float*)stile;   // BM x 64 f32 <= smem
#pragma unroll
    for (int t = 0; t < TI; t++)
        wmma::store_matrix_sync(cs + (m_w + t * 16) * 64 + n_w, facc[t], 64, wmma::mem_row_major);
    __syncthreads();

    // ---- scalar, layout-free fused epilogue ----
    for (int idx = tid; idx < BM * 64; idx += 256) {
        int row = idx >> 6, col = idx & 63;
        float v = fmaxf(cs[idx] + sbias[col], 0.0f);
        size_t ob = (size_t)(bm + row) * N + bn + col;
        float p = v;
        if (add_pair) p += add_pair[ob];
        bf16 h, m, l;
        split3(p, h, m, l);
        Chi[ob] = h; Cmi[ob] = m; Clo[ob] = l;
        if (aux_out) aux_out[ob] = add_aux[ob] + v;
        if (act_out) act_out[ob] = v;
    }
}

// ---- fused weight prep: both W1^T and W2^T 3-term splits in ONE launch ----
// z=0: W1 (K=512, N=1024); z=1: W2 (K=1024, N=512)
__global__ void transpose_split_all(
    const float* __restrict__ W1, bf16* __restrict__ T1h, bf16* __restrict__ T1m, bf16* __restrict__ T1l,
    const float* __restrict__ W2, bf16* __restrict__ T2h, bf16* __restrict__ T2m, bf16* __restrict__ T2l)
{
    const float* W; bf16 *Th, *Tm, *Tl; int K, N;
    if (blockIdx.z == 0) { W = W1; Th = T1h; Tm = T1m; Tl = T1l; K = 512;  N = 1024; }
    else                 { W = W2; Th = T2h; Tm = T2m; Tl = T2l; K = 1024; N = 512;  }
    int nb = blockIdx.x * 32, kb = blockIdx.y * 32;
    if (nb >= N || kb >= K) return;

    __shared__ float t[32][33];
    int tx = threadIdx.x, ty = threadIdx.y;
#pragma unroll
    for (int i = 0; i < 32; i += 8)
        t[ty + i][tx] = W[(size_t)(kb + ty + i) * N + nb + tx];
    __syncthreads();
#pragma unroll
    for (int i = 0; i < 32; i += 8) {
        int n = nb + ty + i, k = kb + tx;
        bf16 h, m, l;
        split3(t[tx][ty + i], h, m, l);
        Th[(size_t)n * K + k] = h;
        Tm[(size_t)n * K + k] = m;
        Tl[(size_t)n * K + k] = l;
    }
}

// ---- conv1 + relu + pool ----
__global__ void conv1_pool_kernel(const float* __restrict__ in, const float* __restrict__ w,
                                  const float* __restrict__ bias, float* __restrict__ out)
{
    int i = blockIdx.x * blockDim.x + threadIdx.x;
    if (i >= BATCH * 16 * 196) return;
    int x = i % 14, y = (i / 14) % 14, c = (i / 196) % 16, b = i / 3136;
    float wv[9];
#pragma unroll
    for (int j = 0; j < 9; j++) wv[j] = w[c * 9 + j];
    float bz = bias[c], m = 0.0f;
    const float* ip = in + (size_t)b * 784;
#pragma unroll
    for (int dy = 0; dy < 2; dy++)
#pragma unroll
        for (int dx = 0; dx < 2; dx++) {
            int Y = 2 * y + dy, X = 2 * x + dx;
            float s = bz;
#pragma unroll
            for (int ky = 0; ky < 3; ky++) {
                int iy = Y + ky - 1; if (iy < 0 || iy >= 28) continue;
#pragma unroll
                for (int kx = 0; kx < 3; kx++) {
                    int ix = X + kx - 1; if (ix < 0 || ix >= 28) continue;
                    s += ip[iy * 28 + ix] * wv[ky * 3 + kx];
                }
            }
            m = fmaxf(m, fmaxf(s, 0.0f));
        }
    out[i] = m;
}

__global__ __launch_bounds__(256) void conv2_pool_kernel(
    const float* __restrict__ in, const float* __restrict__ w,
    const float* __restrict__ bias, float* __restrict__ out)
{
    __shared__ float sin_[3136];
    __shared__ float sw_[4608];
    int b = blockIdx.x, tid = threadIdx.x;
    for (int i = tid; i < 3136; i += 256) sin_[i] = in[(size_t)b * 3136 + i];
    for (int i = tid; i < 4608; i += 256) sw_[i] = w[i];
    __syncthreads();
    for (int o = tid; o < 32 * 49; o += 256) {
        int c = o / 49, rem = o % 49, y = rem / 7, x = rem % 7;
        float bz = bias[c], m = 0.0f;
#pragma unroll
        for (int dy = 0; dy < 2; dy++)
#pragma unroll
            for (int dx = 0; dx < 2; dx++) {
                int Y = 2 * y + dy, X = 2 * x + dx;
                float s = bz;
                for (int ci = 0; ci < 16; ci++)
#pragma unroll
                    for (int ky = 0; ky < 3; ky++) {
                        int iy = Y + ky - 1; if (iy < 0 || iy >= 14) continue;
#pragma unroll
                        for (int kx = 0; kx < 3; kx++) {
                            int ix = X + kx - 1; if (ix < 0 || ix >= 14) continue;
                            s += sin_[ci * 196 + iy * 14 + ix] * sw_[(c * 16 + ci) * 9 + ky * 3 + kx];
                        }
                    }
                m = fmaxf(m, fmaxf(s, 0.0f));
            }
        out[(size_t)b * 1568 + o] = m;
    }
}

// ---- fp32 SGEMM (proj + head). Optional fused recursion-state setup:
// if se_h != null (proj2): inp=C; io = C+oe; (sah,sam,sal) = split3(io+le). ----
template <int BM, int TM>
__global__ __launch_bounds__(256) void gemm_kernel(
    const float* __restrict__ A0, const float* __restrict__ B,
    const float* __restrict__ bias, float* __restrict__ C,
    int M, int N, int K, int doRelu,
    const float* __restrict__ oe, const float* __restrict__ le,
    float* __restrict__ io_out,
    bf16* __restrict__ se_h, bf16* __restrict__ se_m, bf16* __restrict__ se_l)
{
    constexpr int BN = 64, BK = 16;
    constexpr int LA = (BM * BK) / 1024;
    __shared__ __align__(16) float As[BK][BM];
    __shared__ __align__(16) float Bs[BK][BN];
    const int tid = threadIdx.x;
    const int bm = blockIdx.y * BM, bn = blockIdx.x * BN;
    const int n0 = (tid & 15) * 4, m0 = (tid >> 4) * TM;
    const int bRow = tid >> 4, bCol = (tid & 15) * 4;
    float acc[TM][4] = {};
    float4 ra[LA]; float rb[4];
    const int KT = K / BK;
#pragma unroll
    for (int i = 0; i < LA; i++) {
        int idx4 = tid + i * 256; int r = idx4 >> 2, c = (idx4 & 3) << 2;
        ra[i] = *(const float4*)(A0 + (size_t)(bm + r) * K + c);
    }
#pragma unroll
    for (int j = 0; j < 4; j++) {
        int col = bn + bCol + j;
        rb[j] = (col < N) ? B[(size_t)bRow * N + col] : 0.0f;
    }
#pragma unroll
    for (int i = 0; i < LA; i++) {
        int idx4 = tid + i * 256; int r = idx4 >> 2, c = (idx4 & 3) << 2;
        As[c][r] = ra[i].x; As[c+1][r] = ra[i].y; As[c+2][r] = ra[i].z; As[c+3][r] = ra[i].w;
    }
#pragma unroll
    for (int j = 0; j < 4; j++) Bs[bRow][bCol + j] = rb[j];
    __syncthreads();
    for (int kt = 0; kt < KT; kt++) {
        const int k0n = (kt + 1) * BK;
        const bool nx = (kt + 1 < KT);
        if (nx) {
#pragma unroll
            for (int i = 0; i < LA; i++) {
                int idx4 = tid + i * 256; int r = idx4 >> 2, c = (idx4 & 3) << 2;
                ra[i] = *(const float4*)(A0 + (size_t)(bm + r) * K + k0n + c);
            }
#pragma unroll
            for (int j = 0; j < 4; j++) {
                int col = bn + bCol + j;
                rb[j] = (col < N) ? B[(size_t)(k0n + bRow) * N + col] : 0.0f;
            }
        }
#pragma unroll
        for (int k = 0; k < BK; k++) {
            float a[TM], b4[4];
#pragma unroll
            for (int i = 0; i < TM; i += 4) {
                float4 av = *(const float4*)&As[k][m0 + i];
                a[i] = av.x; a[i+1] = av.y; a[i+2] = av.z; a[i+3] = av.w;
            }
            float4 bv = *(const float4*)&Bs[k][n0];
            b4[0] = bv.x; b4[1] = bv.y; b4[2] = bv.z; b4[3] = bv.w;
#pragma unroll
            for (int i = 0; i < TM; i++)
#pragma unroll
                for (int j = 0; j < 4; j++) acc[i][j] += a[i] * b4[j];
        }
        __syncthreads();
        if (nx) {
#pragma unroll
            for (int i = 0; i < LA; i++) {
                int idx4 = tid + i * 256; int r = idx4 >> 2, c = (idx4 & 3) << 2;
                As[c][r] = ra[i].x; As[c+1][r] = ra[i].y; As[c+2][r] = ra[i].z; As[c+3][r] = ra[i].w;
            }
#pragma unroll
            for (int j = 0; j < 4; j++) Bs[bRow][bCol + j] = rb[j];
            __syncthreads();
        }
    }
#pragma unroll
    for (int i = 0; i < TM; i++)
#pragma unroll
        for (int j = 0; j < 4; j++) {
            int col = bn + n0 + j;
            if (col < N) {
                float v = acc[i][j] + bias[col];
                if (doRelu) v = fmaxf(v, 0.0f);
                size_t ob = (size_t)(bm + m0 + i) * N + col;
                C[ob] = v;
                if (se_h) {          // fused setup_state (proj2 only)
                    float io_v = v + oe[ob];
                    io_out[ob] = io_v;
                    bf16 h, m, l;
                    split3(io_v + le[ob], h, m, l);
                    se_h[ob] = h; se_m[ob] = m; se_l[ob] = l;
                }
            }
        }
}

extern "C" void kernel_launch(void* const* d_in, const int* in_sizes, int n_in,
                              void* d_out, int out_size)
{
    (void)in_sizes; (void)n_in; (void)out_size;
    const float* raw = (const float*)d_in[0];
    const float* oe  = (const float*)d_in[1];
    const float* le  = (const float*)d_in[2];
    const float* c1w = (const float*)d_in[3];
    const float* c1b = (const float*)d_in[4];
    const float* c2w = (const float*)d_in[5];
    const float* c2b = (const float*)d_in[6];
    const float* pw1 = (const float*)d_in[7];
    const float* pb1 = (const float*)d_in[8];
    const float* pw2 = (const float*)d_in[9];
    const float* pb2 = (const float*)d_in[10];
    const float* bw1 = (const float*)d_in[11];
    const float* bb1 = (const float*)d_in[12];
    const float* bw2 = (const float*)d_in[13];
    const float* bb2 = (const float*)d_in[14];
    const float* hw  = (const float*)d_in[15];
    const float* hb  = (const float*)d_in[16];
    float* out = (float*)d_out;

    float *pool1, *pool2, *t1f, *inp, *io, *li, *outf;
    bf16 *w1h, *w1m, *w1l, *w2h, *w2m, *w2l;
    bf16 *sah, *sam, *sal, *t1h, *t1m, *t1l;
    cudaGetSymbolAddress((void**)&pool1, g_pool1);
    cudaGetSymbolAddress((void**)&pool2, g_pool2);
    cudaGetSymbolAddress((void**)&t1f, g_t1f);
    cudaGetSymbolAddress((void**)&inp, g_inp);
    cudaGetSymbolAddress((void**)&io,  g_io);
    cudaGetSymbolAddress((void**)&li,  g_li);
    cudaGetSymbolAddress((void**)&outf, g_outf);
    cudaGetSymbolAddress((void**)&w1h, g_w1h);
    cudaGetSymbolAddress((void**)&w1m, g_w1m);
    cudaGetSymbolAddress((void**)&w1l, g_w1l);
    cudaGetSymbolAddress((void**)&w2h, g_w2h);
    cudaGetSymbolAddress((void**)&w2m, g_w2m);
    cudaGetSymbolAddress((void**)&w2l, g_w2l);
    cudaGetSymbolAddress((void**)&sah, g_sah);
    cudaGetSymbolAddress((void**)&sam, g_sam);
    cudaGetSymbolAddress((void**)&sal, g_sal);
    cudaGetSymbolAddress((void**)&t1h, g_t1h);
    cudaGetSymbolAddress((void**)&t1m, g_t1m);
    cudaGetSymbolAddress((void**)&t1l, g_t1l);

    // launch 0: fused weight prep (independent of everything else)
    transpose_split_all<<<dim3(32, 32, 2), dim3(32, 8)>>>(
        bw1, w1h, w1m, w1l, bw2, w2h, w2m, w2l);
    // launches 1-2: CNN
    conv1_pool_kernel<<<(BATCH * 16 * 196 + 255) / 256, 256>>>(raw, c1w, c1b, pool1);   // 1
    conv2_pool_kernel<<<BATCH, 256>>>(pool1, c2w, c2b, pool2);                          // 2
    // launch 3: proj1
    gemm_kernel<128, 8><<<dim3(16, 8), 256>>>(pool2, pw1, pb1, t1f, BATCH, 1024, 1568, 1,
        nullptr, nullptr, nullptr, nullptr, nullptr, nullptr);
    // launch 4: proj2 + fused setup_state (io = inp+oe; sA = split3(io+le))
    gemm_kernel<64, 4><<<dim3(8, 16), 256>>>(t1f, pw2, pb2, inp, BATCH, 512, 1024, 1,
        oe, le, io, sah, sam, sal);

    // launch 5 onward: the recursion (ncu -s 5 -c 1 profiles the first wmma_gemm)
    const dim3 g1(16, 16);  // GEMM1: 64x64 tiles -> 256 CTAs
    const dim3 g2(8, 32);   // GEMM2: 32x64 tiles -> 256 CTAs (occ-2 co-residency)
    const int STEPS = NSUP * 3;
    for (int s = 0; s < STEPS; s++) {
        for (int j = 0; j < NLAT; j++) {
            // t1 = relu(x @ W1 + b1)
            wmma_gemm<64><<<g1, 256>>>(sah, sam, sal, w1h, w1m, w1l, bb1,
                nullptr, nullptr, t1h, t1m, t1l, nullptr, nullptr, 1024, 512);
            if (j < NLAT - 1)
                // lat = relu(t1@W2+b2); next x = io + lat
                wmma_gemm<32><<<g2, 256>>>(t1h, t1m, t1l, w2h, w2m, w2l, bb2,
                    io, nullptr, sah, sam, sal, nullptr, nullptr, 512, 1024);
            else
                // last latent: next x = inp + lat; li = inp + lat
                wmma_gemm<32><<<g2, 256>>>(t1h, t1m, t1l, w2h, w2m, w2l, bb2,
                    inp, inp, sah, sam, sal, li, nullptr, 512, 1024);
        }
        // out step: t1 = relu((inp+lat) @ W1 + b1)
        wmma_gemm<64><<<g1, 256>>>(sah, sam, sal, w1h, w1m, w1l, bb1,
            nullptr, nullptr, t1h, t1m, t1l, nullptr, nullptr, 1024, 512);
        // out = relu(t1@W2+b2); next x = li + out; io = inp + out; (+outf last)
        wmma_gemm<32><<<g2, 256>>>(t1h, t1m, t1l, w2h, w2m, w2l, bb2,
            li, inp, sah, sam, sal, io, (s == STEPS - 1) ? outf : nullptr, 512, 1024);
    }
    // logits = outf @ head_w + head_b
    gemm_kernel<64, 4><<<dim3(1, 16), 256>>>(outf, hw, hb, out, BATCH, 10, 512, 0,
        nullptr, nullptr, nullptr, nullptr, nullptr, nullptr);
}

// round 17
// speedup vs baseline: 1.7545x; 1.7545x over previous
#include <cuda_runtime.h>
#include <cuda_bf16.h>
#include <mma.h>
#include <cstdint>
#include <math.h>

using namespace nvcuda;
typedef __nv_bfloat16 bf16;

#define BATCH 1024
#define NSUP 16
#define NLAT 6

// ---- scratch (__device__ globals; allocation forbidden) ----
__device__ __align__(256) float g_pool1[BATCH * 16 * 14 * 14];
__device__ __align__(256) float g_pool2[BATCH * 32 * 7 * 7];
__device__ __align__(256) float g_t1f [BATCH * 1024];
__device__ __align__(256) float g_inp [BATCH * 512];
__device__ __align__(256) float g_io  [BATCH * 512];   // inp + out
__device__ __align__(256) float g_li  [BATCH * 512];   // inp + lat
__device__ __align__(256) float g_outf[BATCH * 512];
// weights W^T (N x K), 2-term bf16 split
__device__ __align__(256) bf16 g_w1h[1024 * 512], g_w1l[1024 * 512];
__device__ __align__(256) bf16 g_w2h[512 * 1024], g_w2l[512 * 1024];
// activations, 2-term bf16 split
__device__ __align__(256) bf16 g_sah[BATCH * 512],  g_sal[BATCH * 512];
__device__ __align__(256) bf16 g_t1h[BATCH * 1024], g_t1l[BATCH * 1024];

// 2-term split: v = h + l (~17 mantissa bits)
__device__ __forceinline__ void split2(float v, bf16& h, bf16& l) {
    h = __float2bfloat16_rn(v);
    l = __float2bfloat16_rn(v - __bfloat162float(h));
}

// ===========================================================================
// 2-term bf16-split WMMA GEMM with BIAS-FREE ACCUMULATION.
//   C = relu(A @ B^T + bias), A ~ Ah+Al, B ~ Bh+Bl.
//   Per k16: 3 MMAs (hh, hl, lh) into a FRESH-ZERO temp fragment, folded into
//   the master accumulator with fp32 RN adds. The fresh-zero temps defeat the
//   tensor core's truncating accumulator-add bias (R14-measured: 24x error
//   reduction); with the bias killed, the 3rd split term of R14 is redundant
//   -> half the MMA work. BK=64 (half the barriers of R14/15).
// Epilogue: (Chi,Clo) = split2(relu_out + add_pair?) [always],
//   aux_out = relu_out + add_aux [opt], act_out = relu_out [opt].
// Tile 64x64x64, 8 warps (2 in M x 4 in N), RS=72 -> 36.9KB static smem, occ 2.
// ===========================================================================
__global__ __launch_bounds__(256, 2) void wmma_gemm(
    const bf16* __restrict__ Ahi, const bf16* __restrict__ Alo,
    const bf16* __restrict__ Bhi, const bf16* __restrict__ Blo,
    const float* __restrict__ bias,
    const float* __restrict__ add_pair, const float* __restrict__ add_aux,
    bf16* __restrict__ Chi, bf16* __restrict__ Clo,
    float* __restrict__ aux_out, float* __restrict__ act_out,
    int N, int K)
{
    constexpr int RS = 72;                 // row stride in bf16 (144B rows; ldm%8==0)
    __shared__ float sbias[64];
    __shared__ __align__(32) bf16 stile[4 * 64 * RS];   // 36864 B
    bf16* sAh = stile;
    bf16* sAl = stile + 64 * RS;
    bf16* sBh = stile + 2 * 64 * RS;
    bf16* sBl = stile + 3 * 64 * RS;

    const int tid = threadIdx.x, wid = tid >> 5;
    const int bm = blockIdx.y * 64, bn = blockIdx.x * 64;
    const int warp_m = wid & 1, warp_n = wid >> 1;   // 2 x 4 warp grid
    const int m_w = warp_m * 32, n_w = warp_n * 16;
    const int KT = K >> 6;                           // BK = 64

    if (tid < 64) sbias[tid] = bias[bn + tid];

    wmma::fragment<wmma::accumulator, 16, 16, 16, float> facc[2];
    wmma::fill_fragment(facc[0], 0.0f);
    wmma::fill_fragment(facc[1], 0.0f);

    uint4 rah[2], ral[2], rbh[2], rbl[2];

    auto gload = [&](int kt) {
        const int kof = kt * 64;
#pragma unroll
        for (int i = 0; i < 2; i++) {
            int idx = tid + i * 256; int row = idx >> 3, ch = idx & 7;
            size_t oa = (size_t)(bm + row) * K + kof + ch * 8;
            size_t ob = (size_t)(bn + row) * K + kof + ch * 8;
            rah[i] = *(const uint4*)(Ahi + oa);
            ral[i] = *(const uint4*)(Alo + oa);
            rbh[i] = *(const uint4*)(Bhi + ob);
            rbl[i] = *(const uint4*)(Blo + ob);
        }
    };
    auto sstore = [&]() {
#pragma unroll
        for (int i = 0; i < 2; i++) {
            int idx = tid + i * 256; int row = idx >> 3, ch = idx & 7;
            *(uint4*)(sAh + row * RS + ch * 8) = rah[i];
            *(uint4*)(sAl + row * RS + ch * 8) = ral[i];
            *(uint4*)(sBh + row * RS + ch * 8) = rbh[i];
            *(uint4*)(sBl + row * RS + ch * 8) = rbl[i];
        }
    };

    gload(0);
    sstore();
    __syncthreads();

    for (int kt = 0; kt < KT; kt++) {
        if (kt + 1 < KT) gload(kt + 1);   // prefetch next tile into registers

#pragma unroll
        for (int k16 = 0; k16 < 4; k16++) {
            const int kb = k16 * 16;
            wmma::fragment<wmma::matrix_b, 16, 16, 16, bf16, wmma::col_major> fbh, fbl;
            wmma::load_matrix_sync(fbh, sBh + n_w * RS + kb, RS);
            wmma::load_matrix_sync(fbl, sBl + n_w * RS + kb, RS);
#pragma unroll
            for (int ti = 0; ti < 2; ti++) {
                wmma::fragment<wmma::matrix_a, 16, 16, 16, bf16, wmma::row_major> fah, fal;
                wmma::load_matrix_sync(fah, sAh + (m_w + ti * 16) * RS + kb, RS);
                wmma::load_matrix_sync(fal, sAl + (m_w + ti * 16) * RS + kb, RS);
                // fresh-zero temp: keeps |acc| small during HW chained adds
                wmma::fragment<wmma::accumulator, 16, 16, 16, float> ftmp;
                wmma::fill_fragment(ftmp, 0.0f);
                wmma::mma_sync(ftmp, fah, fbh, ftmp);  // h*h
                wmma::mma_sync(ftmp, fah, fbl, ftmp);  // h*l
                wmma::mma_sync(ftmp, fal, fbh, ftmp);  // l*h
#pragma unroll
                for (int e = 0; e < ftmp.num_elements; e++)
                    facc[ti].x[e] += ftmp.x[e];
            }
        }
        __syncthreads();
        if (kt + 1 < KT) { sstore(); __syncthreads(); }
    }

    // ---- stage C to smem (aliases tile memory; safe after the sync above) ----
    float* cs = (float*)stile;   // 64x64 f32 = 16384B <= 36864B
    wmma::store_matrix_sync(cs + (m_w +  0) * 64 + n_w, facc[0], 64, wmma::mem_row_major);
    wmma::store_matrix_sync(cs + (m_w + 16) * 64 + n_w, facc[1], 64, wmma::mem_row_major);
    __syncthreads();

    // ---- scalar, layout-free fused epilogue ----
    for (int idx = tid; idx < 64 * 64; idx += 256) {
        int row = idx >> 6, col = idx & 63;
        float v = fmaxf(cs[idx] + sbias[col], 0.0f);
        size_t ob = (size_t)(bm + row) * N + bn + col;
        float p = v;
        if (add_pair) p += add_pair[ob];
        bf16 h, l;
        split2(p, h, l);
        Chi[ob] = h; Clo[ob] = l;
        if (aux_out) aux_out[ob] = add_aux[ob] + v;
        if (act_out) act_out[ob] = v;
    }
}

// ---- fused weight prep: both W1^T and W2^T 2-term splits in ONE launch ----
__global__ void transpose_split_all(
    const float* __restrict__ W1, bf16* __restrict__ T1h, bf16* __restrict__ T1l,
    const float* __restrict__ W2, bf16* __restrict__ T2h, bf16* __restrict__ T2l)
{
    const float* W; bf16 *Th, *Tl; int K, N;
    if (blockIdx.z == 0) { W = W1; Th = T1h; Tl = T1l; K = 512;  N = 1024; }
    else                 { W = W2; Th = T2h; Tl = T2l; K = 1024; N = 512;  }
    int nb = blockIdx.x * 32, kb = blockIdx.y * 32;
    if (nb >= N || kb >= K) return;

    __shared__ float t[32][33];
    int tx = threadIdx.x, ty = threadIdx.y;
#pragma unroll
    for (int i = 0; i < 32; i += 8)
        t[ty + i][tx] = W[(size_t)(kb + ty + i) * N + nb + tx];
    __syncthreads();
#pragma unroll
    for (int i = 0; i < 32; i += 8) {
        int n = nb + ty + i, k = kb + tx;
        bf16 h, l;
        split2(t[tx][ty + i], h, l);
        Th[(size_t)n * K + k] = h;
        Tl[(size_t)n * K + k] = l;
    }
}

// ---- conv1 + relu + pool ----
__global__ void conv1_pool_kernel(const float* __restrict__ in, const float* __restrict__ w,
                                  const float* __restrict__ bias, float* __restrict__ out)
{
    int i = blockIdx.x * blockDim.x + threadIdx.x;
    if (i >= BATCH * 16 * 196) return;
    int x = i % 14, y = (i / 14) % 14, c = (i / 196) % 16, b = i / 3136;
    float wv[9];
#pragma unroll
    for (int j = 0; j < 9; j++) wv[j] = w[c * 9 + j];
    float bz = bias[c], m = 0.0f;
    const float* ip = in + (size_t)b * 784;
#pragma unroll
    for (int dy = 0; dy < 2; dy++)
#pragma unroll
        for (int dx = 0; dx < 2; dx++) {
            int Y = 2 * y + dy, X = 2 * x + dx;
            float s = bz;
#pragma unroll
            for (int ky = 0; ky < 3; ky++) {
                int iy = Y + ky - 1; if (iy < 0 || iy >= 28) continue;
#pragma unroll
                for (int kx = 0; kx < 3; kx++) {
                    int ix = X + kx - 1; if (ix < 0 || ix >= 28) continue;
                    s += ip[iy * 28 + ix] * wv[ky * 3 + kx];
                }
            }
            m = fmaxf(m, fmaxf(s, 0.0f));
        }
    out[i] = m;
}

__global__ __launch_bounds__(256) void conv2_pool_kernel(
    const float* __restrict__ in, const float* __restrict__ w,
    const float* __restrict__ bias, float* __restrict__ out)
{
    __shared__ float sin_[3136];
    __shared__ float sw_[4608];
    int b = blockIdx.x, tid = threadIdx.x;
    for (int i = tid; i < 3136; i += 256) sin_[i] = in[(size_t)b * 3136 + i];
    for (int i = tid; i < 4608; i += 256) sw_[i] = w[i];
    __syncthreads();
    for (int o = tid; o < 32 * 49; o += 256) {
        int c = o / 49, rem = o % 49, y = rem / 7, x = rem % 7;
        float bz = bias[c], m = 0.0f;
#pragma unroll
        for (int dy = 0; dy < 2; dy++)
#pragma unroll
            for (int dx = 0; dx < 2; dx++) {
                int Y = 2 * y + dy, X = 2 * x + dx;
                float s = bz;
                for (int ci = 0; ci < 16; ci++)
#pragma unroll
                    for (int ky = 0; ky < 3; ky++) {
                        int iy = Y + ky - 1; if (iy < 0 || iy >= 14) continue;
#pragma unroll
                        for (int kx = 0; kx < 3; kx++) {
                            int ix = X + kx - 1; if (ix < 0 || ix >= 14) continue;
                            s += sin_[ci * 196 + iy * 14 + ix] * sw_[(c * 16 + ci) * 9 + ky * 3 + kx];
                        }
                    }
                m = fmaxf(m, fmaxf(s, 0.0f));
            }
        out[(size_t)b * 1568 + o] = m;
    }
}

// ---- fp32 SGEMM (proj + head). Optional fused recursion-state setup:
// if se_h != null (proj2): inp=C; io = C+oe; (sah,sal) = split2(io+le). ----
template <int BM, int TM>
__global__ __launch_bounds__(256) void gemm_kernel(
    const float* __restrict__ A0, const float* __restrict__ B,
    const float* __restrict__ bias, float* __restrict__ C,
    int M, int N, int K, int doRelu,
    const float* __restrict__ oe, const float* __restrict__ le,
    float* __restrict__ io_out,
    bf16* __restrict__ se_h, bf16* __restrict__ se_l)
{
    constexpr int BN = 64, BK = 16;
    constexpr int LA = (BM * BK) / 1024;
    __shared__ __align__(16) float As[BK][BM];
    __shared__ __align__(16) float Bs[BK][BN];
    const int tid = threadIdx.x;
    const int bm = blockIdx.y * BM, bn = blockIdx.x * BN;
    const int n0 = (tid & 15) * 4, m0 = (tid >> 4) * TM;
    const int bRow = tid >> 4, bCol = (tid & 15) * 4;
    float acc[TM][4] = {};
    float4 ra[LA]; float rb[4];
    const int KT = K / BK;
#pragma unroll
    for (int i = 0; i < LA; i++) {
        int idx4 = tid + i * 256; int r = idx4 >> 2, c = (idx4 & 3) << 2;
        ra[i] = *(const float4*)(A0 + (size_t)(bm + r) * K + c);
    }
#pragma unroll
    for (int j = 0; j < 4; j++) {
        int col = bn + bCol + j;
        rb[j] = (col < N) ? B[(size_t)bRow * N + col] : 0.0f;
    }
#pragma unroll
    for (int i = 0; i < LA; i++) {
        int idx4 = tid + i * 256; int r = idx4 >> 2, c = (idx4 & 3) << 2;
        As[c][r] = ra[i].x; As[c+1][r] = ra[i].y; As[c+2][r] = ra[i].z; As[c+3][r] = ra[i].w;
    }
#pragma unroll
    for (int j = 0; j < 4; j++) Bs[bRow][bCol + j] = rb[j];
    __syncthreads();
    for (int kt = 0; kt < KT; kt++) {
        const int k0n = (kt + 1) * BK;
        const bool nx = (kt + 1 < KT);
        if (nx) {
#pragma unroll
            for (int i = 0; i < LA; i++) {
                int idx4 = tid + i * 256; int r = idx4 >> 2, c = (idx4 & 3) << 2;
                ra[i] = *(const float4*)(A0 + (size_t)(bm + r) * K + k0n + c);
            }
#pragma unroll
            for (int j = 0; j < 4; j++) {
                int col = bn + bCol + j;
                rb[j] = (col < N) ? B[(size_t)(k0n + bRow) * N + col] : 0.0f;
            }
        }
#pragma unroll
        for (int k = 0; k < BK; k++) {
            float a[TM], b4[4];
#pragma unroll
            for (int i = 0; i < TM; i += 4) {
                float4 av = *(const float4*)&As[k][m0 + i];
                a[i] = av.x; a[i+1] = av.y; a[i+2] = av.z; a[i+3] = av.w;
            }
            float4 bv = *(const float4*)&Bs[k][n0];
            b4[0] = bv.x; b4[1] = bv.y; b4[2] = bv.z; b4[3] = bv.w;
#pragma unroll
            for (int i = 0; i < TM; i++)
#pragma unroll
                for (int j = 0; j < 4; j++) acc[i][j] += a[i] * b4[j];
        }
        __syncthreads();
        if (nx) {
#pragma unroll
            for (int i = 0; i < LA; i++) {
                int idx4 = tid + i * 256; int r = idx4 >> 2, c = (idx4 & 3) << 2;
                As[c][r] = ra[i].x; As[c+1][r] = ra[i].y; As[c+2][r] = ra[i].z; As[c+3][r] = ra[i].w;
            }
#pragma unroll
            for (int j = 0; j < 4; j++) Bs[bRow][bCol + j] = rb[j];
            __syncthreads();
        }
    }
#pragma unroll
    for (int i = 0; i < TM; i++)
#pragma unroll
        for (int j = 0; j < 4; j++) {
            int col = bn + n0 + j;
            if (col < N) {
                float v = acc[i][j] + bias[col];
                if (doRelu) v = fmaxf(v, 0.0f);
                size_t ob = (size_t)(bm + m0 + i) * N + col;
                C[ob] = v;
                if (se_h) {          // fused setup_state (proj2 only)
                    float io_v = v + oe[ob];
                    io_out[ob] = io_v;
                    bf16 h, l;
                    split2(io_v + le[ob], h, l);
                    se_h[ob] = h; se_l[ob] = l;
                }
            }
        }
}

extern "C" void kernel_launch(void* const* d_in, const int* in_sizes, int n_in,
                              void* d_out, int out_size)
{
    (void)in_sizes; (void)n_in; (void)out_size;
    const float* raw = (const float*)d_in[0];
    const float* oe  = (const float*)d_in[1];
    const float* le  = (const float*)d_in[2];
    const float* c1w = (const float*)d_in[3];
    const float* c1b = (const float*)d_in[4];
    const float* c2w = (const float*)d_in[5];
    const float* c2b = (const float*)d_in[6];
    const float* pw1 = (const float*)d_in[7];
    const float* pb1 = (const float*)d_in[8];
    const float* pw2 = (const float*)d_in[9];
    const float* pb2 = (const float*)d_in[10];
    const float* bw1 = (const float*)d_in[11];
    const float* bb1 = (const float*)d_in[12];
    const float* bw2 = (const float*)d_in[13];
    const float* bb2 = (const float*)d_in[14];
    const float* hw  = (const float*)d_in[15];
    const float* hb  = (const float*)d_in[16];
    float* out = (float*)d_out;

    float *pool1, *pool2, *t1f, *inp, *io, *li, *outf;
    bf16 *w1h, *w1l, *w2h, *w2l, *sah, *sal, *t1h, *t1l;
    cudaGetSymbolAddress((void**)&pool1, g_pool1);
    cudaGetSymbolAddress((void**)&pool2, g_pool2);
    cudaGetSymbolAddress((void**)&t1f, g_t1f);
    cudaGetSymbolAddress((void**)&inp, g_inp);
    cudaGetSymbolAddress((void**)&io,  g_io);
    cudaGetSymbolAddress((void**)&li,  g_li);
    cudaGetSymbolAddress((void**)&outf, g_outf);
    cudaGetSymbolAddress((void**)&w1h, g_w1h);
    cudaGetSymbolAddress((void**)&w1l, g_w1l);
    cudaGetSymbolAddress((void**)&w2h, g_w2h);
    cudaGetSymbolAddress((void**)&w2l, g_w2l);
    cudaGetSymbolAddress((void**)&sah, g_sah);
    cudaGetSymbolAddress((void**)&sal, g_sal);
    cudaGetSymbolAddress((void**)&t1h, g_t1h);
    cudaGetSymbolAddress((void**)&t1l, g_t1l);

    // weight prep (independent) + CNN + proj (setup fused into proj2)
    transpose_split_all<<<dim3(32, 32, 2), dim3(32, 8)>>>(bw1, w1h, w1l, bw2, w2h, w2l);
    conv1_pool_kernel<<<(BATCH * 16 * 196 + 255) / 256, 256>>>(raw, c1w, c1b, pool1);
    conv2_pool_kernel<<<BATCH, 256>>>(pool1, c2w, c2b, pool2);
    gemm_kernel<128, 8><<<dim3(16, 8), 256>>>(pool2, pw1, pb1, t1f, BATCH, 1024, 1568, 1,
        nullptr, nullptr, nullptr, nullptr, nullptr);
    gemm_kernel<64, 4><<<dim3(8, 16), 256>>>(t1f, pw2, pb2, inp, BATCH, 512, 1024, 1,
        oe, le, io, sah, sal);

    const dim3 g1(16, 16);  // GEMM1: N=1024 -> 256 CTAs
    const dim3 g2(8, 16);   // GEMM2: N=512  -> 128 CTAs
    const int STEPS = NSUP * 3;
    for (int s = 0; s < STEPS; s++) {
        for (int j = 0; j < NLAT; j++) {
            // t1 = relu(x @ W1 + b1)
            wmma_gemm<<<g1, 256>>>(sah, sal, w1h, w1l, bb1,
                nullptr, nullptr, t1h, t1l, nullptr, nullptr, 1024, 512);
            if (j < NLAT - 1)
                // lat = relu(t1@W2+b2); next x = io + lat
                wmma_gemm<<<g2, 256>>>(t1h, t1l, w2h, w2l, bb2,
                    io, nullptr, sah, sal, nullptr, nullptr, 512, 1024);
            else
                // last latent: next x = inp + lat; li = inp + lat
                wmma_gemm<<<g2, 256>>>(t1h, t1l, w2h, w2l, bb2,
                    inp, inp, sah, sal, li, nullptr, 512, 1024);
        }
        // out step: t1 = relu((inp+lat) @ W1 + b1)
        wmma_gemm<<<g1, 256>>>(sah, sal, w1h, w1l, bb1,
            nullptr, nullptr, t1h, t1l, nullptr, nullptr, 1024, 512);
        // out = relu(t1@W2+b2); next x = li + out; io = inp + out; (+outf last)
        wmma_gemm<<<g2, 256>>>(t1h, t1l, w2h, w2l, bb2,
            li, inp, sah, sal, io, (s == STEPS - 1) ? outf : nullptr, 512, 1024);
    }
    // logits = outf @ head_w + head_b
    gemm_kernel<64, 4><<<dim3(1, 16), 256>>>(outf, hw, hb, out, BATCH, 10, 512, 0,
        nullptr, nullptr, nullptr, nullptr, nullptr);
}